// round 1
// baseline (speedup 1.0000x reference)
#include <cuda_runtime.h>

// Problem constants
#define NN      4
#define BPTS    8192
#define CIN     32
#define DOUT    32
#define ANB     32
#define NBAS    36          // 4 radii * 9 SH
#define TOTAL   (NN*BPTS)   // 32768 points
#define GROUPS  (TOTAL/8)   // 4096 groups of 8 points

// Scratch (device globals -- no allocation allowed)
__device__ float g_inputT[NN*BPTS*CIN];     // input transposed to (n,b,c)
__device__ float g_wperm[288*32*4];          // W permuted: [g=c*9+s][d][r]

// ---------------- f32x2 helpers (sm_103a packed fp32) ----------------
__device__ __forceinline__ unsigned long long pack2(float x, float y){
    unsigned long long r; asm("mov.b64 %0,{%1,%2};" : "=l"(r) : "f"(x), "f"(y)); return r;
}
__device__ __forceinline__ void unpack2(unsigned long long v, float& x, float& y){
    asm("mov.b64 {%0,%1},%2;" : "=f"(x), "=f"(y) : "l"(v));
}
__device__ __forceinline__ unsigned long long fma2(unsigned long long a, unsigned long long b, unsigned long long c){
    unsigned long long d; asm("fma.rn.f32x2 %0,%1,%2,%3;" : "=l"(d) : "l"(a), "l"(b), "l"(c)); return d;
}
__device__ __forceinline__ unsigned long long mul2(unsigned long long a, unsigned long long b){
    unsigned long long d; asm("mul.rn.f32x2 %0,%1,%2;" : "=l"(d) : "l"(a), "l"(b)); return d;
}
__device__ __forceinline__ void lds128(const float* p, unsigned long long& a, unsigned long long& b){
    unsigned s = (unsigned)__cvta_generic_to_shared(p);
    asm volatile("ld.shared.v2.u64 {%0,%1},[%2];" : "=l"(a), "=l"(b) : "r"(s));
}
__device__ __forceinline__ void sts128(float* p, unsigned long long a, unsigned long long b){
    unsigned s = (unsigned)__cvta_generic_to_shared(p);
    asm volatile("st.shared.v2.u64 [%0],{%1,%2};" :: "r"(s), "l"(a), "l"(b));
}

// ---------------- prep kernels ----------------
// Transpose input (n,c,b) -> (n,b,c) for coalesced channel gathers.
__global__ void prep_transpose(const float* __restrict__ in){
    __shared__ float t[32][33];
    int n = blockIdx.y;
    int b0 = blockIdx.x * 32;
    int tx = threadIdx.x, ty = threadIdx.y;       // block (32,8)
    #pragma unroll
    for (int i = ty; i < 32; i += 8)
        t[i][tx] = in[(n*CIN + i)*BPTS + b0 + tx];
    __syncthreads();
    #pragma unroll
    for (int i = ty; i < 32; i += 8)
        g_inputT[(n*BPTS + b0 + i)*CIN + tx] = t[tx][i];
}

// Permute W[d][c][r*9+s] -> wperm[(c*9+s)*128 + d*4 + r]
__global__ void prep_w(const float* __restrict__ W){
    int t = blockIdx.x * 256 + threadIdx.x;
    if (t >= 288*32*4) return;
    int r = t & 3;
    int d = (t >> 2) & 31;
    int g = t >> 7;
    int c = g / 9, s = g - c*9;
    g_wperm[t] = W[(d*CIN + c)*NBAS + r*9 + s];
}

// ---------------- main kernel ----------------
// smem: WS 36864 f | geom 7168 f | Msh 9216 f | red 2304 f  => 222208 bytes
#define SM_WS   0
#define SM_GEOM 36864
#define SM_MSH  (36864 + 7168)
#define SM_RED  (36864 + 7168 + 9216)
#define SM_FLOATS (36864 + 7168 + 9216 + 2304)

__global__ void __launch_bounds__(256, 1)
se3_main(const float* __restrict__ coords,
         const float* __restrict__ rmask,
         const int*   __restrict__ nbrs,
         float*       __restrict__ out)
{
    extern __shared__ float smem[];
    float* WS    = smem + SM_WS;
    float* geomS = smem + SM_GEOM;
    float* MshS  = smem + SM_MSH;
    float* redS  = smem + SM_RED;

    const int tid  = threadIdx.x;
    const int w    = tid >> 5;
    const int lane = tid & 31;

    // Load W into smem once per CTA (persistent over groups)
    {
        const float4* src = (const float4*)g_wperm;
        float4* dst = (float4*)WS;
        for (int i = tid; i < 288*32; i += 256) dst[i] = src[i];
    }
    __syncthreads();

    for (int grp = blockIdx.x; grp < GROUPS; grp += gridDim.x) {
        const int flat = grp*8 + w;            // this warp's point
        const int n = flat >> 13;
        // ---------------- Phase A: geometry (lane = neighbor a) ----------------
        const int nb_idx = flat*ANB + lane;
        const int j   = nbrs[nb_idx];
        const float msk = rmask[nb_idx];
        const float* cc = coords + (long)flat*3;
        const float c0x = cc[0], c0y = cc[1], c0z = cc[2];
        const float* cj = coords + ((long)(n*BPTS + j))*3;
        const float dx = cj[0]-c0x, dy = cj[1]-c0y, dz = cj[2]-c0z;
        const float r2 = dx*dx + dy*dy + dz*dz;
        const float r  = sqrtf(r2);
        const float inv = __fdividef(1.0f, r + 1e-8f);
        const float ux = dx*inv, uy = dy*inv, uz = dz*inv;
        const float y0 = 0.28209479f;
        const float y1 = 0.48860251f*ux, y2 = 0.48860251f*uy, y3 = 0.48860251f*uz;
        const float y4 = 1.09254843f*ux*uy, y5 = 1.09254843f*uy*uz;
        const float y6 = 0.31539157f*(3.0f*uz*uz - 1.0f);
        const float y7 = 1.09254843f*ux*uz;
        const float y8 = 0.54627421f*(ux*ux - uy*uy);
        float rb[4];
        #pragma unroll
        for (int i = 0; i < 4; i++){
            float tt = (r - 0.5f*(float)(i+1)) * 2.0f;
            rb[i] = msk * __expf(-tt*tt);      // mask folded into radial basis
        }
        // geom row (28 floats, pad keeps STS conflicts low):
        // [0..3]=rb, [4..21] = Y duplicated pairs, [22..27] pad
        float* grow = geomS + (w*32 + lane)*28;
        sts128(grow + 0,  pack2(rb[0], rb[1]), pack2(rb[2], rb[3]));
        sts128(grow + 4,  pack2(y0, y0), pack2(y1, y1));
        sts128(grow + 8,  pack2(y2, y2), pack2(y3, y3));
        sts128(grow + 12, pack2(y4, y4), pack2(y5, y5));
        sts128(grow + 16, pack2(y6, y6), pack2(y7, y7));
        sts128(grow + 20, pack2(y8, y8), pack2(0.f, 0.f));
        __syncwarp();

        // ---------------- Phase A: feature gather (lane = channel c) ----------------
        float feat[32];
        #pragma unroll
        for (int a = 0; a < 32; a++){
            int ja = __shfl_sync(0xffffffffu, j, a);
            feat[a] = __ldg(&g_inputT[((long)(n*BPTS + ja))*CIN + lane]);
        }

        // ---------------- Phase A: M accumulation (rank-1 rb x Y) ----------------
        // M01[s] = (M[r0][s], M[r1][s]) ; M23[s] = (M[r2][s], M[r3][s])
        unsigned long long M01[9], M23[9];
        #pragma unroll
        for (int s = 0; s < 9; s++){ M01[s] = 0ull; M23[s] = 0ull; }
        #pragma unroll
        for (int a = 0; a < 32; a++){
            const float* g = geomS + (w*32 + a)*28;
            unsigned long long rb01, rb23, yd[10];
            lds128(g + 0,  rb01,  rb23);
            lds128(g + 4,  yd[0], yd[1]);
            lds128(g + 8,  yd[2], yd[3]);
            lds128(g + 12, yd[4], yd[5]);
            lds128(g + 16, yd[6], yd[7]);
            lds128(g + 20, yd[8], yd[9]);
            unsigned long long f2 = pack2(feat[a], feat[a]);
            unsigned long long frb01 = mul2(f2, rb01);
            unsigned long long frb23 = mul2(f2, rb23);
            #pragma unroll
            for (int s = 0; s < 9; s++){
                M01[s] = fma2(frb01, yd[s], M01[s]);
                M23[s] = fma2(frb23, yd[s], M23[s]);
            }
        }
        // write M to smem in k' = s*4 + r order (float4-aligned)
        {
            float* mrow = MshS + w*1152 + lane*36;
            #pragma unroll
            for (int s = 0; s < 9; s++)
                sts128(mrow + s*4, M01[s], M23[s]);
        }
        __syncthreads();

        // ---------------- Phase B: W contraction (lane = d, warps split ck') ----------------
        unsigned long long acc[8];
        #pragma unroll
        for (int p = 0; p < 8; p++) acc[p] = 0ull;
        const int g0 = w*36;
        #pragma unroll 4
        for (int gi = 0; gi < 36; gi++){
            const int g = g0 + gi;
            unsigned long long w01, w23;
            lds128(WS + (g*32 + lane)*4, w01, w23);     // conflict-free
            const float* mbase = MshS + g*4;
            #pragma unroll
            for (int p = 0; p < 8; p++){
                unsigned long long m01, m23;
                lds128(mbase + p*1152, m01, m23);       // broadcast
                acc[p] = fma2(m01, w01, acc[p]);
                acc[p] = fma2(m23, w23, acc[p]);
            }
        }
        #pragma unroll
        for (int p = 0; p < 8; p++){
            float lo, hi; unpack2(acc[p], lo, hi);
            redS[w*288 + lane*9 + p] = lo + hi;         // red[w][d][p], pad 9
        }
        __syncthreads();

        // ---------------- final cross-warp reduce + coalesced-ish store ----------------
        {
            const int d = tid >> 3;
            const int p = tid & 7;
            float s = 0.f;
            #pragma unroll
            for (int ww = 0; ww < 8; ww++)
                s += redS[ww*288 + d*9 + p];
            const int flatp = grp*8 + p;
            const int nn = flatp >> 13;
            const int bb = flatp & (BPTS-1);
            out[((long)(nn*DOUT + d))*BPTS + bb] = s;
        }
        // no trailing barrier needed: next group's Msh writes are fenced by the
        // pre-phase-B __syncthreads, and redS writes by the post-Msh one.
    }
}

// ---------------- launch ----------------
extern "C" void kernel_launch(void* const* d_in, const int* in_sizes, int n_in,
                              void* d_out, int out_size)
{
    const float* input  = (const float*)d_in[0];
    const float* coords = (const float*)d_in[1];
    const float* rmask  = (const float*)d_in[2];
    const float* W      = (const float*)d_in[3];
    const int*   nbrs   = (const int*)d_in[4];
    float* out = (float*)d_out;

    (void)in_sizes; (void)n_in; (void)out_size;

    // prep: transpose input, permute W
    dim3 tb(32, 8), tg(BPTS/32, NN);
    prep_transpose<<<tg, tb>>>(input);
    prep_w<<<(288*32*4 + 255)/256, 256>>>(W);

    // main: persistent CTAs, one per SM
    int dev = 0; cudaGetDevice(&dev);
    int smcount = 148;
    cudaDeviceGetAttribute(&smcount, cudaDevAttrMultiProcessorCount, dev);

    size_t shmem = (size_t)SM_FLOATS * sizeof(float);  // 222208 B
    cudaFuncSetAttribute(se3_main, cudaFuncAttributeMaxDynamicSharedMemorySize, (int)shmem);
    se3_main<<<smcount, 256, shmem>>>(coords, rmask, nbrs, out);
}

// round 2
// speedup vs baseline: 1.1367x; 1.1367x over previous
#include <cuda_runtime.h>

// Problem constants
#define NN      4
#define BPTS    8192
#define CIN     32
#define DOUT    32
#define ANB     32
#define NBAS    36          // 4 radii * 9 SH
#define TOTAL   (NN*BPTS)   // 32768 points
#define PPI     16          // points per CTA iteration
#define NITER   (TOTAL/PPI) // 2048
#define THREADS 512

// Scratch (device globals -- no allocation allowed)
__device__ float g_inputT[NN*BPTS*CIN];     // input transposed to (n,b,c)
__device__ float g_wperm[288*32*4];          // W permuted: [g=c*9+s][d][r]

// ---------------- f32x2 helpers (sm_103a packed fp32) ----------------
__device__ __forceinline__ unsigned long long pack2(float x, float y){
    unsigned long long r; asm("mov.b64 %0,{%1,%2};" : "=l"(r) : "f"(x), "f"(y)); return r;
}
__device__ __forceinline__ void unpack2(unsigned long long v, float& x, float& y){
    asm("mov.b64 {%0,%1},%2;" : "=f"(x), "=f"(y) : "l"(v));
}
__device__ __forceinline__ unsigned long long fma2(unsigned long long a, unsigned long long b, unsigned long long c){
    unsigned long long d; asm("fma.rn.f32x2 %0,%1,%2,%3;" : "=l"(d) : "l"(a), "l"(b), "l"(c)); return d;
}
__device__ __forceinline__ unsigned long long mul2(unsigned long long a, unsigned long long b){
    unsigned long long d; asm("mul.rn.f32x2 %0,%1,%2;" : "=l"(d) : "l"(a), "l"(b)); return d;
}
__device__ __forceinline__ void lds128(const float* p, unsigned long long& a, unsigned long long& b){
    unsigned s = (unsigned)__cvta_generic_to_shared(p);
    asm volatile("ld.shared.v2.u64 {%0,%1},[%2];" : "=l"(a), "=l"(b) : "r"(s));
}
__device__ __forceinline__ void sts128(float* p, unsigned long long a, unsigned long long b){
    unsigned s = (unsigned)__cvta_generic_to_shared(p);
    asm volatile("st.shared.v2.u64 [%0],{%1,%2};" :: "r"(s), "l"(a), "l"(b));
}

// ---------------- prep kernels ----------------
// Transpose input (n,c,b) -> (n,b,c) for coalesced channel gathers.
__global__ void prep_transpose(const float* __restrict__ in){
    __shared__ float t[32][33];
    int n = blockIdx.y;
    int b0 = blockIdx.x * 32;
    int tx = threadIdx.x, ty = threadIdx.y;       // block (32,8)
    #pragma unroll
    for (int i = ty; i < 32; i += 8)
        t[i][tx] = in[(n*CIN + i)*BPTS + b0 + tx];
    __syncthreads();
    #pragma unroll
    for (int i = ty; i < 32; i += 8)
        g_inputT[(n*BPTS + b0 + i)*CIN + tx] = t[tx][i];
}

// Permute W[d][c][r*9+s] -> wperm[(c*9+s)*128 + d*4 + r]
__global__ void prep_w(const float* __restrict__ W){
    int t = blockIdx.x * 256 + threadIdx.x;
    if (t >= 288*32*4) return;
    int r = t & 3;
    int d = (t >> 2) & 31;
    int g = t >> 7;
    int c = g / 9, s = g - c*9;
    g_wperm[t] = W[(d*CIN + c)*NBAS + r*9 + s];
}

// ---------------- main kernel ----------------
// smem layout (floats):
//   geomS: 16 warps * 32 nbrs * 28        = 14336
//   MshS : 16 pts   * 1152 (c*36+s*4+r)   = 18432
//   redS : 16 warps * 16 pts * 32 d       =  8192
// total 40960 floats = 163840 bytes
#define GSTRIDE 28
#define SM_GEOM 0
#define SM_MSH  (16*32*GSTRIDE)
#define SM_RED  (SM_MSH + PPI*1152)
#define SM_FLOATS (SM_RED + 16*PPI*32)

__global__ void __launch_bounds__(THREADS, 1)
se3_main(const float* __restrict__ coords,
         const float* __restrict__ rmask,
         const int*   __restrict__ nbrs,
         float*       __restrict__ out)
{
    extern __shared__ float smem[];
    float* geomS = smem + SM_GEOM;
    float* MshS  = smem + SM_MSH;
    float* redS  = smem + SM_RED;

    const int tid  = threadIdx.x;
    const int w    = tid >> 5;      // 0..15
    const int lane = tid & 31;

    for (int grp = blockIdx.x; grp < NITER; grp += gridDim.x) {
        const int flat = grp*PPI + w;          // this warp's point
        const int n = flat >> 13;

        // ---------------- Phase A: geometry (lane = neighbor a) ----------------
        const int nb_idx = flat*ANB + lane;
        const int j   = nbrs[nb_idx];
        const float msk = rmask[nb_idx];
        const float* cc = coords + (long)flat*3;
        const float c0x = cc[0], c0y = cc[1], c0z = cc[2];
        const float* cj = coords + ((long)(n*BPTS + j))*3;
        const float dx = cj[0]-c0x, dy = cj[1]-c0y, dz = cj[2]-c0z;
        const float r2 = dx*dx + dy*dy + dz*dz;
        const float r  = sqrtf(r2);
        const float inv = __fdividef(1.0f, r + 1e-8f);
        const float ux = dx*inv, uy = dy*inv, uz = dz*inv;
        const float y0 = 0.28209479f;
        const float y1 = 0.48860251f*ux, y2 = 0.48860251f*uy, y3 = 0.48860251f*uz;
        const float y4 = 1.09254843f*ux*uy, y5 = 1.09254843f*uy*uz;
        const float y6 = 0.31539157f*(3.0f*uz*uz - 1.0f);
        const float y7 = 1.09254843f*ux*uz;
        const float y8 = 0.54627421f*(ux*ux - uy*uy);
        float rb[4];
        #pragma unroll
        for (int i = 0; i < 4; i++){
            float tt = (r - 0.5f*(float)(i+1)) * 2.0f;
            rb[i] = msk * __expf(-tt*tt);      // mask folded into radial basis
        }
        // geom row: [0..3]=rb pairs, [4..21] = Y duplicated pairs, [22..27] pad
        float* grow = geomS + (w*32 + lane)*GSTRIDE;
        sts128(grow + 0,  pack2(rb[0], rb[1]), pack2(rb[2], rb[3]));
        sts128(grow + 4,  pack2(y0, y0), pack2(y1, y1));
        sts128(grow + 8,  pack2(y2, y2), pack2(y3, y3));
        sts128(grow + 12, pack2(y4, y4), pack2(y5, y5));
        sts128(grow + 16, pack2(y6, y6), pack2(y7, y7));
        sts128(grow + 20, pack2(y8, y8), pack2(0.f, 0.f));
        __syncwarp();

        // ---------------- Phase A: M accumulation with feat prefetch ----------------
        const float* inrow = g_inputT + (((long)n << 13) * CIN) + lane;
        float fpre0, fpre1, fpre2, fpre3;
        {
            int j0 = __shfl_sync(0xffffffffu, j, 0);
            int j1 = __shfl_sync(0xffffffffu, j, 1);
            int j2 = __shfl_sync(0xffffffffu, j, 2);
            int j3 = __shfl_sync(0xffffffffu, j, 3);
            fpre0 = __ldg(inrow + (long)j0*CIN);
            fpre1 = __ldg(inrow + (long)j1*CIN);
            fpre2 = __ldg(inrow + (long)j2*CIN);
            fpre3 = __ldg(inrow + (long)j3*CIN);
        }
        unsigned long long M01[9], M23[9];
        #pragma unroll
        for (int s = 0; s < 9; s++){ M01[s] = 0ull; M23[s] = 0ull; }

        #pragma unroll
        for (int a4 = 0; a4 < 32; a4 += 4){
            #pragma unroll
            for (int q = 0; q < 4; q++){
                const int a = a4 + q;
                const float* g = geomS + (w*32 + a)*GSTRIDE;
                unsigned long long rb01, rb23, yd[10];
                lds128(g + 0,  rb01,  rb23);
                lds128(g + 4,  yd[0], yd[1]);
                lds128(g + 8,  yd[2], yd[3]);
                lds128(g + 12, yd[4], yd[5]);
                lds128(g + 16, yd[6], yd[7]);
                lds128(g + 20, yd[8], yd[9]);
                float f;
                if (q == 0) f = fpre0; else if (q == 1) f = fpre1;
                else if (q == 2) f = fpre2; else f = fpre3;
                // prefetch a+4
                if (a4 + 4 < 32){
                    int jn = __shfl_sync(0xffffffffu, j, a + 4);
                    float fn = __ldg(inrow + (long)jn*CIN);
                    if (q == 0) fpre0 = fn; else if (q == 1) fpre1 = fn;
                    else if (q == 2) fpre2 = fn; else fpre3 = fn;
                }
                unsigned long long f2 = pack2(f, f);
                unsigned long long frb01 = mul2(f2, rb01);
                unsigned long long frb23 = mul2(f2, rb23);
                #pragma unroll
                for (int s = 0; s < 9; s++){
                    M01[s] = fma2(frb01, yd[s], M01[s]);
                    M23[s] = fma2(frb23, yd[s], M23[s]);
                }
            }
        }
        // write M to smem: Msh[p= w][c*36 + s*4 + r]  (stride 36: conflict-free per octet)
        {
            float* mrow = MshS + w*1152 + lane*36;
            #pragma unroll
            for (int s = 0; s < 9; s++)
                sts128(mrow + s*4, M01[s], M23[s]);
        }
        __syncthreads();

        // ---------------- Phase B: W contraction ----------------
        // warp w owns g in [w*18, w*18+18); lane = d; W rows streamed via LDG (L2-resident)
        unsigned long long acc[PPI];
        #pragma unroll
        for (int p = 0; p < PPI; p++) acc[p] = 0ull;
        const int g0 = w*18;
        const ulonglong2* wrow = (const ulonglong2*)(g_wperm + ((long)g0*32 + lane)*4);
        ulonglong2 wv = __ldg(wrow);
        #pragma unroll
        for (int gi = 0; gi < 18; gi++){
            ulonglong2 wnext;
            if (gi < 17) wnext = __ldg(wrow + (gi+1)*32);
            const float* mbase = MshS + (g0 + gi)*4;
            #pragma unroll
            for (int p = 0; p < PPI; p++){
                unsigned long long m01, m23;
                lds128(mbase + p*1152, m01, m23);   // broadcast
                acc[p] = fma2(m01, wv.x, acc[p]);
                acc[p] = fma2(m23, wv.y, acc[p]);
            }
            wv = wnext;
        }
        #pragma unroll
        for (int p = 0; p < PPI; p++){
            float lo, hi; unpack2(acc[p], lo, hi);
            redS[w*(PPI*32) + p*32 + lane] = lo + hi;   // red[w][p][d], conflict-free
        }
        __syncthreads();

        // ---------------- final cross-warp reduce + store ----------------
        {
            const int p = w;          // tid>>5
            const int d = lane;       // tid&31
            float s = 0.f;
            #pragma unroll
            for (int ww = 0; ww < 16; ww++)
                s += redS[ww*(PPI*32) + p*32 + d];
            const int flatp = grp*PPI + p;
            const int nn = flatp >> 13;
            const int bb = flatp & (BPTS-1);
            out[((long)(nn*DOUT + d))*BPTS + bb] = s;
        }
        // 2 barriers/iter suffice: Msh reads complete before sync#2; red reads
        // (reduce) complete before the next iteration's sync#1, which precedes
        // the next red writes.
    }
}

// ---------------- launch ----------------
extern "C" void kernel_launch(void* const* d_in, const int* in_sizes, int n_in,
                              void* d_out, int out_size)
{
    const float* input  = (const float*)d_in[0];
    const float* coords = (const float*)d_in[1];
    const float* rmask  = (const float*)d_in[2];
    const float* W      = (const float*)d_in[3];
    const int*   nbrs   = (const int*)d_in[4];
    float* out = (float*)d_out;

    (void)in_sizes; (void)n_in; (void)out_size;

    // prep: transpose input, permute W
    dim3 tb(32, 8), tg(BPTS/32, NN);
    prep_transpose<<<tg, tb>>>(input);
    prep_w<<<(288*32*4 + 255)/256, 256>>>(W);

    // main: persistent CTAs, one per SM
    int dev = 0; cudaGetDevice(&dev);
    int smcount = 148;
    cudaDeviceGetAttribute(&smcount, cudaDevAttrMultiProcessorCount, dev);

    size_t shmem = (size_t)SM_FLOATS * sizeof(float);  // 163840 B
    cudaFuncSetAttribute(se3_main, cudaFuncAttributeMaxDynamicSharedMemorySize, (int)shmem);
    se3_main<<<smcount, THREADS, shmem>>>(coords, rmask, nbrs, out);
}

// round 3
// speedup vs baseline: 1.1383x; 1.0014x over previous
#include <cuda_runtime.h>

// Problem constants
#define NN      4
#define BPTS    8192
#define CIN     32
#define DOUT    32
#define ANB     32
#define NBAS    36          // 4 radii * 9 SH
#define TOTAL   (NN*BPTS)   // 32768 points
#define PPI     16          // points per CTA iteration
#define NITER   (TOTAL/PPI) // 2048
#define THREADS 512

// Scratch (device globals -- no allocation allowed)
__device__ float g_inputT[NN*BPTS*CIN];     // input transposed to (n,b,c)
__device__ float g_wperm[288*32*4];          // W permuted: [g=c*9+s][d][r]

// ---------------- f32x2 helpers (sm_103a packed fp32) ----------------
__device__ __forceinline__ unsigned long long pack2(float x, float y){
    unsigned long long r; asm("mov.b64 %0,{%1,%2};" : "=l"(r) : "f"(x), "f"(y)); return r;
}
__device__ __forceinline__ void unpack2(unsigned long long v, float& x, float& y){
    asm("mov.b64 {%0,%1},%2;" : "=f"(x), "=f"(y) : "l"(v));
}
__device__ __forceinline__ unsigned long long fma2(unsigned long long a, unsigned long long b, unsigned long long c){
    unsigned long long d; asm("fma.rn.f32x2 %0,%1,%2,%3;" : "=l"(d) : "l"(a), "l"(b), "l"(c)); return d;
}
__device__ __forceinline__ unsigned long long mul2(unsigned long long a, unsigned long long b){
    unsigned long long d; asm("mul.rn.f32x2 %0,%1,%2;" : "=l"(d) : "l"(a), "l"(b)); return d;
}
__device__ __forceinline__ void lds128(const float* p, unsigned long long& a, unsigned long long& b){
    unsigned s = (unsigned)__cvta_generic_to_shared(p);
    asm volatile("ld.shared.v2.u64 {%0,%1},[%2];" : "=l"(a), "=l"(b) : "r"(s));
}
__device__ __forceinline__ void sts128(float* p, unsigned long long a, unsigned long long b){
    unsigned s = (unsigned)__cvta_generic_to_shared(p);
    asm volatile("st.shared.v2.u64 [%0],{%1,%2};" :: "r"(s), "l"(a), "l"(b));
}

// ---------------- fused prep kernel ----------------
// blocks [0,1024): transpose input (n,c,b) -> (n,b,c)
// blocks [1024,1168): permute W[d][c][r*9+s] -> wperm[(c*9+s)*128 + d*4 + r]
__global__ void prep_all(const float* __restrict__ in, const float* __restrict__ W){
    const int bx = blockIdx.x;
    const int tid = threadIdx.x;           // 256
    if (bx < 1024){
        __shared__ float t[32][33];
        const int n  = bx >> 8;
        const int b0 = (bx & 255) * 32;
        const int tx = tid & 31, ty = tid >> 5;   // ty 0..7
        #pragma unroll
        for (int i = ty; i < 32; i += 8)
            t[i][tx] = in[(n*CIN + i)*BPTS + b0 + tx];
        __syncthreads();
        #pragma unroll
        for (int i = ty; i < 32; i += 8)
            g_inputT[(n*BPTS + b0 + i)*CIN + tx] = t[tx][i];
    } else {
        int t = (bx - 1024)*256 + tid;
        if (t < 288*32*4){
            int r = t & 3;
            int d = (t >> 2) & 31;
            int g = t >> 7;
            int c = g / 9, s = g - c*9;
            g_wperm[t] = W[(d*CIN + c)*NBAS + r*9 + s];
        }
    }
}

// ---------------- main kernel ----------------
// smem layout (floats):
//   geomS: 16 warps * 32 nbrs * 28        = 14336
//   MshS : 16 pts   * 1152 (c*36+s*4+r)   = 18432
//   redS : 16 warps * 16 pts * 32 d       =  8192
// total 40960 floats = 163840 bytes
#define GSTRIDE 28
#define SM_GEOM 0
#define SM_MSH  (16*32*GSTRIDE)
#define SM_RED  (SM_MSH + PPI*1152)
#define SM_FLOATS (SM_RED + 16*PPI*32)

__global__ void __launch_bounds__(THREADS, 1)
se3_main(const float* __restrict__ coords,
         const float* __restrict__ rmask,
         const int*   __restrict__ nbrs,
         float*       __restrict__ out)
{
    extern __shared__ float smem[];
    float* geomS = smem + SM_GEOM;
    float* MshS  = smem + SM_MSH;
    float* redS  = smem + SM_RED;

    const int tid  = threadIdx.x;
    const int w    = tid >> 5;      // 0..15
    const int lane = tid & 31;

    for (int grp = blockIdx.x; grp < NITER; grp += gridDim.x) {
        const int flat = grp*PPI + w;          // this warp's point
        const int n = flat >> 13;

        // ---------------- Phase A: geometry (lane = neighbor a) ----------------
        const int nb_idx = flat*ANB + lane;
        const int j   = nbrs[nb_idx];
        const float msk = rmask[nb_idx];
        const float* cc = coords + (long)flat*3;
        const float c0x = cc[0], c0y = cc[1], c0z = cc[2];
        const float* cj = coords + ((long)(n*BPTS + j))*3;
        const float dx = cj[0]-c0x, dy = cj[1]-c0y, dz = cj[2]-c0z;
        const float r2 = dx*dx + dy*dy + dz*dz;
        const float r  = sqrtf(r2);
        const float inv = __fdividef(1.0f, r + 1e-8f);
        const float ux = dx*inv, uy = dy*inv, uz = dz*inv;
        const float y0 = 0.28209479f;
        const float y1 = 0.48860251f*ux, y2 = 0.48860251f*uy, y3 = 0.48860251f*uz;
        const float y4 = 1.09254843f*ux*uy, y5 = 1.09254843f*uy*uz;
        const float y6 = 0.31539157f*(3.0f*uz*uz - 1.0f);
        const float y7 = 1.09254843f*ux*uz;
        const float y8 = 0.54627421f*(ux*ux - uy*uy);
        float rb[4];
        #pragma unroll
        for (int i = 0; i < 4; i++){
            float tt = (r - 0.5f*(float)(i+1)) * 2.0f;
            rb[i] = msk * __expf(-tt*tt);      // mask folded into radial basis
        }
        // geom row: [0..3]=rb pairs, [4..21] = Y duplicated pairs, [22..27] pad
        float* grow = geomS + (w*32 + lane)*GSTRIDE;
        sts128(grow + 0,  pack2(rb[0], rb[1]), pack2(rb[2], rb[3]));
        sts128(grow + 4,  pack2(y0, y0), pack2(y1, y1));
        sts128(grow + 8,  pack2(y2, y2), pack2(y3, y3));
        sts128(grow + 12, pack2(y4, y4), pack2(y5, y5));
        sts128(grow + 16, pack2(y6, y6), pack2(y7, y7));
        sts128(grow + 20, pack2(y8, y8), pack2(0.f, 0.f));
        __syncwarp();

        // ---------------- Phase A: M accumulation, feat prefetch depth 8 ----------------
        const float* inrow = g_inputT + (((long)n << 13) * CIN) + lane;
        float fp[8];
        #pragma unroll
        for (int q = 0; q < 8; q++){
            int jq = __shfl_sync(0xffffffffu, j, q);
            fp[q] = __ldg(inrow + (long)jq*CIN);
        }
        unsigned long long M01[9], M23[9];
        #pragma unroll
        for (int s = 0; s < 9; s++){ M01[s] = 0ull; M23[s] = 0ull; }

        #pragma unroll
        for (int a8 = 0; a8 < 32; a8 += 8){
            #pragma unroll
            for (int q = 0; q < 8; q++){
                const int a = a8 + q;
                const float* g = geomS + (w*32 + a)*GSTRIDE;
                unsigned long long rb01, rb23, yd[10];
                lds128(g + 0,  rb01,  rb23);
                lds128(g + 4,  yd[0], yd[1]);
                lds128(g + 8,  yd[2], yd[3]);
                lds128(g + 12, yd[4], yd[5]);
                lds128(g + 16, yd[6], yd[7]);
                lds128(g + 20, yd[8], yd[9]);
                const float f = fp[q];
                // prefetch a+8
                if (a8 + 8 < 32){
                    int jn = __shfl_sync(0xffffffffu, j, a + 8);
                    fp[q] = __ldg(inrow + (long)jn*CIN);
                }
                unsigned long long f2 = pack2(f, f);
                unsigned long long frb01 = mul2(f2, rb01);
                unsigned long long frb23 = mul2(f2, rb23);
                #pragma unroll
                for (int s = 0; s < 9; s++){
                    M01[s] = fma2(frb01, yd[s], M01[s]);
                    M23[s] = fma2(frb23, yd[s], M23[s]);
                }
            }
        }
        // write M to smem: Msh[p=w][c*36 + s*4 + r]
        {
            float* mrow = MshS + w*1152 + lane*36;
            #pragma unroll
            for (int s = 0; s < 9; s++)
                sts128(mrow + s*4, M01[s], M23[s]);
        }
        __syncthreads();

        // ---------------- Phase B: W contraction ----------------
        // warp w owns g in [w*18, w*18+18); lane = d; W rows via LDG (L2), prefetch depth 2
        unsigned long long acc[PPI];
        #pragma unroll
        for (int p = 0; p < PPI; p++) acc[p] = 0ull;
        const int g0 = w*18;
        const ulonglong2* wrow = (const ulonglong2*)(g_wperm + ((long)g0*32 + lane)*4);
        ulonglong2 wv0 = __ldg(wrow);
        ulonglong2 wv1 = __ldg(wrow + 32);
        #pragma unroll
        for (int gi = 0; gi < 18; gi++){
            const ulonglong2 wc = (gi & 1) ? wv1 : wv0;
            if (gi + 2 < 18){
                if (gi & 1) wv1 = __ldg(wrow + (gi+2)*32);
                else        wv0 = __ldg(wrow + (gi+2)*32);
            }
            const float* mbase = MshS + (g0 + gi)*4;
            unsigned long long m0[8], m1[8];
            #pragma unroll
            for (int p = 0; p < 8; p++) lds128(mbase + p*1152, m0[p], m1[p]);
            #pragma unroll
            for (int p = 0; p < 8; p++){
                acc[p] = fma2(m0[p], wc.x, acc[p]);
                acc[p] = fma2(m1[p], wc.y, acc[p]);
            }
            #pragma unroll
            for (int p = 0; p < 8; p++) lds128(mbase + (p+8)*1152, m0[p], m1[p]);
            #pragma unroll
            for (int p = 0; p < 8; p++){
                acc[p+8] = fma2(m0[p], wc.x, acc[p+8]);
                acc[p+8] = fma2(m1[p], wc.y, acc[p+8]);
            }
        }
        #pragma unroll
        for (int p = 0; p < PPI; p++){
            float lo, hi; unpack2(acc[p], lo, hi);
            redS[w*(PPI*32) + p*32 + lane] = lo + hi;   // red[w][p][d], conflict-free
        }
        __syncthreads();

        // ---------------- final cross-warp reduce + store ----------------
        {
            const int p = w;          // tid>>5
            const int d = lane;       // tid&31
            float s = 0.f;
            #pragma unroll
            for (int ww = 0; ww < 16; ww++)
                s += redS[ww*(PPI*32) + p*32 + d];
            const int flatp = grp*PPI + p;
            const int nn = flatp >> 13;
            const int bb = flatp & (BPTS-1);
            out[((long)(nn*DOUT + d))*BPTS + bb] = s;
        }
        // 2 barriers/iter suffice: Msh reads complete before sync#2; red reads
        // (reduce) complete before the next iteration's sync#1, which precedes
        // the next red writes.
    }
}

// ---------------- launch ----------------
extern "C" void kernel_launch(void* const* d_in, const int* in_sizes, int n_in,
                              void* d_out, int out_size)
{
    const float* input  = (const float*)d_in[0];
    const float* coords = (const float*)d_in[1];
    const float* rmask  = (const float*)d_in[2];
    const float* W      = (const float*)d_in[3];
    const int*   nbrs   = (const int*)d_in[4];
    float* out = (float*)d_out;

    (void)in_sizes; (void)n_in; (void)out_size;

    // fused prep: transpose input + permute W (1024 + 144 blocks)
    prep_all<<<1168, 256>>>(input, W);

    // main: persistent CTAs, one per SM
    int dev = 0; cudaGetDevice(&dev);
    int smcount = 148;
    cudaDeviceGetAttribute(&smcount, cudaDevAttrMultiProcessorCount, dev);

    size_t shmem = (size_t)SM_FLOATS * sizeof(float);  // 163840 B
    cudaFuncSetAttribute(se3_main, cudaFuncAttributeMaxDynamicSharedMemorySize, (int)shmem);
    se3_main<<<smcount, THREADS, shmem>>>(coords, rmask, nbrs, out);
}

// round 4
// speedup vs baseline: 1.1703x; 1.0281x over previous
#include <cuda_runtime.h>

// Problem constants
#define NN      4
#define BPTS    8192
#define CIN     32
#define DOUT    32
#define ANB     32
#define NBAS    36            // 4 radii * 9 SH
#define TOTAL   (NN*BPTS)     // 32768 points
#define PPI     8             // points per CTA iteration (= warps)
#define WARPS   8
#define THREADS 256
#define NITER   (TOTAL/PPI)   // 4096

// Scratch (device globals -- no allocation allowed)
__device__ float g_inputT[NN*BPTS*CIN];     // input transposed to (n,b,c)
__device__ float g_wperm[288*32*4];          // W permuted: [g=c*9+s][d][r]

// ---------------- f32x2 helpers (sm_103a packed fp32) ----------------
__device__ __forceinline__ unsigned long long pack2(float x, float y){
    unsigned long long r; asm("mov.b64 %0,{%1,%2};" : "=l"(r) : "f"(x), "f"(y)); return r;
}
__device__ __forceinline__ void unpack2(unsigned long long v, float& x, float& y){
    asm("mov.b64 {%0,%1},%2;" : "=f"(x), "=f"(y) : "l"(v));
}
__device__ __forceinline__ unsigned long long fma2(unsigned long long a, unsigned long long b, unsigned long long c){
    unsigned long long d; asm("fma.rn.f32x2 %0,%1,%2,%3;" : "=l"(d) : "l"(a), "l"(b), "l"(c)); return d;
}
__device__ __forceinline__ unsigned long long mul2(unsigned long long a, unsigned long long b){
    unsigned long long d; asm("mul.rn.f32x2 %0,%1,%2;" : "=l"(d) : "l"(a), "l"(b)); return d;
}
__device__ __forceinline__ void lds128(const float* p, unsigned long long& a, unsigned long long& b){
    unsigned s = (unsigned)__cvta_generic_to_shared(p);
    asm volatile("ld.shared.v2.u64 {%0,%1},[%2];" : "=l"(a), "=l"(b) : "r"(s));
}
__device__ __forceinline__ void sts128(float* p, unsigned long long a, unsigned long long b){
    unsigned s = (unsigned)__cvta_generic_to_shared(p);
    asm volatile("st.shared.v2.u64 [%0],{%1,%2};" :: "r"(s), "l"(a), "l"(b));
}

// ---------------- fused prep kernel ----------------
__global__ void prep_all(const float* __restrict__ in, const float* __restrict__ W){
    const int bx = blockIdx.x;
    const int tid = threadIdx.x;           // 256
    if (bx < 1024){
        __shared__ float t[32][33];
        const int n  = bx >> 8;
        const int b0 = (bx & 255) * 32;
        const int tx = tid & 31, ty = tid >> 5;
        #pragma unroll
        for (int i = ty; i < 32; i += 8)
            t[i][tx] = in[(n*CIN + i)*BPTS + b0 + tx];
        __syncthreads();
        #pragma unroll
        for (int i = ty; i < 32; i += 8)
            g_inputT[(n*BPTS + b0 + i)*CIN + tx] = t[tx][i];
    } else {
        int t = (bx - 1024)*256 + tid;
        if (t < 288*32*4){
            int r = t & 3;
            int d = (t >> 2) & 31;
            int g = t >> 7;
            int c = g / 9, s = g - c*9;
            g_wperm[t] = W[(d*CIN + c)*NBAS + r*9 + s];
        }
    }
}

// ---------------- main kernel ----------------
// smem (floats):
//   geomS: 8 warps * 32 nbrs * 20 (13 used)  = 5120
//   MshS : 8 pts   * 1152 (c*36+s*4+r)       = 9216
//   redS : 8 warps * 8 pts * 33 (32 used)    = 2112
// total 16448 floats = 65792 bytes / CTA; 2 CTAs per SM.
#define GSTRIDE 20
#define RED_STRIDE 33
#define SM_GEOM 0
#define SM_MSH  (WARPS*32*GSTRIDE)
#define SM_RED  (SM_MSH + PPI*1152)
#define SM_FLOATS (SM_RED + WARPS*PPI*RED_STRIDE)

__global__ void __launch_bounds__(THREADS, 2)
se3_main(const float* __restrict__ coords,
         const float* __restrict__ rmask,
         const int*   __restrict__ nbrs,
         float*       __restrict__ out)
{
    extern __shared__ float smem[];
    float* geomS = smem + SM_GEOM;
    float* MshS  = smem + SM_MSH;
    float* redS  = smem + SM_RED;

    const int tid  = threadIdx.x;
    const int w    = tid >> 5;      // 0..7
    const int lane = tid & 31;

    for (int grp = blockIdx.x; grp < NITER; grp += gridDim.x) {
        const int flat = grp*PPI + w;          // this warp's point
        const int n = flat >> 13;

        // ---------------- Phase A: geometry (lane = neighbor a) ----------------
        const int nb_idx = flat*ANB + lane;
        const int j   = nbrs[nb_idx];
        const float msk = rmask[nb_idx];
        const float* cc = coords + (long)flat*3;
        const float c0x = cc[0], c0y = cc[1], c0z = cc[2];
        const float* cj = coords + ((long)(n*BPTS + j))*3;
        const float dx = cj[0]-c0x, dy = cj[1]-c0y, dz = cj[2]-c0z;
        const float r2 = dx*dx + dy*dy + dz*dz;
        const float r  = sqrtf(r2);
        const float inv = __fdividef(1.0f, r + 1e-8f);
        const float ux = dx*inv, uy = dy*inv, uz = dz*inv;
        const float y0 = 0.28209479f;
        const float y1 = 0.48860251f*ux, y2 = 0.48860251f*uy, y3 = 0.48860251f*uz;
        const float y4 = 1.09254843f*ux*uy, y5 = 1.09254843f*uy*uz;
        const float y6 = 0.31539157f*(3.0f*uz*uz - 1.0f);
        const float y7 = 1.09254843f*ux*uz;
        const float y8 = 0.54627421f*(ux*ux - uy*uy);
        float rb[4];
        #pragma unroll
        for (int i = 0; i < 4; i++){
            float tt = (r - 0.5f*(float)(i+1)) * 2.0f;
            rb[i] = msk * __expf(-tt*tt);      // mask folded into radial basis
        }
        // geom row: [0..3]=rb quad, [4..11]=y0..y7, [12]=y8 (13 unique floats)
        float* grow = geomS + (w*32 + lane)*GSTRIDE;
        sts128(grow + 0, pack2(rb[0], rb[1]), pack2(rb[2], rb[3]));
        sts128(grow + 4, pack2(y0, y1), pack2(y2, y3));
        sts128(grow + 8, pack2(y4, y5), pack2(y6, y7));
        grow[12] = y8;
        __syncwarp();

        // ---------------- Phase A: M accumulation, feat prefetch depth 8 ----------------
        const float* inrow = g_inputT + (((long)n << 13) * CIN) + lane;
        float fp[8];
        #pragma unroll
        for (int q = 0; q < 8; q++){
            int jq = __shfl_sync(0xffffffffu, j, q);
            fp[q] = __ldg(inrow + (long)jq*CIN);
        }
        unsigned long long M01[9], M23[9];
        #pragma unroll
        for (int s = 0; s < 9; s++){ M01[s] = 0ull; M23[s] = 0ull; }

        #pragma unroll
        for (int a8 = 0; a8 < 32; a8 += 8){
            #pragma unroll
            for (int q = 0; q < 8; q++){
                const int a = a8 + q;
                const float* g = geomS + (w*32 + a)*GSTRIDE;
                unsigned long long rb01, rb23;
                lds128(g + 0, rb01, rb23);
                const float4 ya = *(const float4*)(g + 4);
                const float4 yb = *(const float4*)(g + 8);
                const float  yc = g[12];
                const float f = fp[q];
                if (a8 + 8 < 32){
                    int jn = __shfl_sync(0xffffffffu, j, a + 8);
                    fp[q] = __ldg(inrow + (long)jn*CIN);
                }
                unsigned long long f2 = pack2(f, f);
                unsigned long long frb01 = mul2(f2, rb01);
                unsigned long long frb23 = mul2(f2, rb23);
                unsigned long long yd[9];
                yd[0] = pack2(ya.x, ya.x); yd[1] = pack2(ya.y, ya.y);
                yd[2] = pack2(ya.z, ya.z); yd[3] = pack2(ya.w, ya.w);
                yd[4] = pack2(yb.x, yb.x); yd[5] = pack2(yb.y, yb.y);
                yd[6] = pack2(yb.z, yb.z); yd[7] = pack2(yb.w, yb.w);
                yd[8] = pack2(yc, yc);
                #pragma unroll
                for (int s = 0; s < 9; s++){
                    M01[s] = fma2(frb01, yd[s], M01[s]);
                    M23[s] = fma2(frb23, yd[s], M23[s]);
                }
            }
        }
        // write M to smem: Msh[p=w][c*36 + s*4 + r]
        {
            float* mrow = MshS + w*1152 + lane*36;
            #pragma unroll
            for (int s = 0; s < 9; s++)
                sts128(mrow + s*4, M01[s], M23[s]);
        }
        __syncthreads();

        // ---------------- Phase B: W contraction ----------------
        // warp w owns g in [w*36, w*36+36); lane = d; W rows via LDG (L2), prefetch depth 2
        unsigned long long acc[PPI];
        #pragma unroll
        for (int p = 0; p < PPI; p++) acc[p] = 0ull;
        const int g0 = w*36;
        const ulonglong2* wrow = (const ulonglong2*)(g_wperm + ((long)g0*32 + lane)*4);
        ulonglong2 wv0 = __ldg(wrow);
        ulonglong2 wv1 = __ldg(wrow + 32);
        #pragma unroll
        for (int gi = 0; gi < 36; gi++){
            const ulonglong2 wc = (gi & 1) ? wv1 : wv0;
            if (gi + 2 < 36){
                if (gi & 1) wv1 = __ldg(wrow + (gi+2)*32);
                else        wv0 = __ldg(wrow + (gi+2)*32);
            }
            const float* mbase = MshS + (g0 + gi)*4;
            unsigned long long m0[PPI], m1[PPI];
            #pragma unroll
            for (int p = 0; p < PPI; p++) lds128(mbase + p*1152, m0[p], m1[p]);
            #pragma unroll
            for (int p = 0; p < PPI; p++){
                acc[p] = fma2(m0[p], wc.x, acc[p]);
                acc[p] = fma2(m1[p], wc.y, acc[p]);
            }
        }
        #pragma unroll
        for (int p = 0; p < PPI; p++){
            float lo, hi; unpack2(acc[p], lo, hi);
            redS[(w*PPI + p)*RED_STRIDE + lane] = lo + hi;   // red[w][p][d]
        }
        __syncthreads();

        // ---------------- final cross-warp reduce + store ----------------
        {
            const int d = tid >> 3;      // 0..31
            const int p = tid & 7;       // 0..7
            float s = 0.f;
            #pragma unroll
            for (int ww = 0; ww < WARPS; ww++)
                s += redS[(ww*PPI + p)*RED_STRIDE + d];
            const int flatp = grp*PPI + p;
            const int nn = flatp >> 13;
            const int bb = flatp & (BPTS-1);
            out[((long)(nn*DOUT + d))*BPTS + bb] = s;
        }
        // 2 barriers/iter: Msh reads done before sync#2; red reads (reduce)
        // done before the next iteration's sync#1, which precedes red writes.
    }
}

// ---------------- launch ----------------
extern "C" void kernel_launch(void* const* d_in, const int* in_sizes, int n_in,
                              void* d_out, int out_size)
{
    const float* input  = (const float*)d_in[0];
    const float* coords = (const float*)d_in[1];
    const float* rmask  = (const float*)d_in[2];
    const float* W      = (const float*)d_in[3];
    const int*   nbrs   = (const int*)d_in[4];
    float* out = (float*)d_out;

    (void)in_sizes; (void)n_in; (void)out_size;

    // fused prep: transpose input + permute W (1024 + 144 blocks)
    prep_all<<<1168, 256>>>(input, W);

    // main: persistent CTAs, two per SM
    int dev = 0; cudaGetDevice(&dev);
    int smcount = 148;
    cudaDeviceGetAttribute(&smcount, cudaDevAttrMultiProcessorCount, dev);

    size_t shmem = (size_t)SM_FLOATS * sizeof(float);  // 65792 B
    cudaFuncSetAttribute(se3_main, cudaFuncAttributeMaxDynamicSharedMemorySize, (int)shmem);
    se3_main<<<2*smcount, THREADS, shmem>>>(coords, rmask, nbrs, out);
}

// round 5
// speedup vs baseline: 1.1782x; 1.0068x over previous
#include <cuda_runtime.h>

// Problem constants
#define NN      4
#define BPTS    8192
#define CIN     32
#define DOUT    32
#define ANB     32
#define NBAS    36            // 4 radii * 9 SH
#define TOTAL   (NN*BPTS)     // 32768 points
#define PPI     8             // points per CTA iteration (= warps)
#define WARPS   8
#define THREADS 256
#define NITER   (TOTAL/PPI)   // 4096

// Scratch (device globals -- no allocation allowed)
__device__ float g_inputT[NN*BPTS*CIN];     // input transposed to (n,b,c)
__device__ float g_wperm[288*32*4];          // W permuted: [g=c*9+s][d][r]

// ---------------- f32x2 helpers (sm_103a packed fp32) ----------------
__device__ __forceinline__ unsigned long long pack2(float x, float y){
    unsigned long long r; asm("mov.b64 %0,{%1,%2};" : "=l"(r) : "f"(x), "f"(y)); return r;
}
__device__ __forceinline__ void unpack2(unsigned long long v, float& x, float& y){
    asm("mov.b64 {%0,%1},%2;" : "=f"(x), "=f"(y) : "l"(v));
}
__device__ __forceinline__ unsigned long long fma2(unsigned long long a, unsigned long long b, unsigned long long c){
    unsigned long long d; asm("fma.rn.f32x2 %0,%1,%2,%3;" : "=l"(d) : "l"(a), "l"(b), "l"(c)); return d;
}
__device__ __forceinline__ unsigned long long mul2(unsigned long long a, unsigned long long b){
    unsigned long long d; asm("mul.rn.f32x2 %0,%1,%2;" : "=l"(d) : "l"(a), "l"(b)); return d;
}
__device__ __forceinline__ void lds128(const float* p, unsigned long long& a, unsigned long long& b){
    unsigned s = (unsigned)__cvta_generic_to_shared(p);
    asm volatile("ld.shared.v2.u64 {%0,%1},[%2];" : "=l"(a), "=l"(b) : "r"(s));
}
__device__ __forceinline__ void sts128(float* p, unsigned long long a, unsigned long long b){
    unsigned s = (unsigned)__cvta_generic_to_shared(p);
    asm volatile("st.shared.v2.u64 [%0],{%1,%2};" :: "r"(s), "l"(a), "l"(b));
}

// ---------------- fused prep kernel ----------------
__global__ void prep_all(const float* __restrict__ in, const float* __restrict__ W){
    const int bx = blockIdx.x;
    const int tid = threadIdx.x;           // 256
    if (bx < 1024){
        __shared__ float t[32][33];
        const int n  = bx >> 8;
        const int b0 = (bx & 255) * 32;
        const int tx = tid & 31, ty = tid >> 5;
        #pragma unroll
        for (int i = ty; i < 32; i += 8)
            t[i][tx] = in[(n*CIN + i)*BPTS + b0 + tx];
        __syncthreads();
        #pragma unroll
        for (int i = ty; i < 32; i += 8)
            g_inputT[(n*BPTS + b0 + i)*CIN + tx] = t[tx][i];
    } else {
        int t = (bx - 1024)*256 + tid;
        if (t < 288*32*4){
            int r = t & 3;
            int d = (t >> 2) & 31;
            int g = t >> 7;
            int c = g / 9, s = g - c*9;
            g_wperm[t] = W[(d*CIN + c)*NBAS + r*9 + s];
        }
    }
}

// ---------------- main kernel ----------------
// smem (floats):
//   geomS: 8 warps * 32 nbrs * 20 (13 used)  = 5120
//   MshS : 8 pts   * 1152 (c*36+s*4+r)       = 9216
//   redS : 8 warps * 8 pts * 33 (32 used)    = 2112
// total 16448 floats = 65792 bytes / CTA; 2 CTAs per SM.
#define GSTRIDE 20
#define RED_STRIDE 33
#define SM_GEOM 0
#define SM_MSH  (WARPS*32*GSTRIDE)
#define SM_RED  (SM_MSH + PPI*1152)
#define SM_FLOATS (SM_RED + WARPS*PPI*RED_STRIDE)

__global__ void __launch_bounds__(THREADS, 2)
se3_main(const float* __restrict__ coords,
         const float* __restrict__ rmask,
         const int*   __restrict__ nbrs,
         float*       __restrict__ out)
{
    extern __shared__ float smem[];
    float* geomS = smem + SM_GEOM;
    float* MshS  = smem + SM_MSH;
    float* redS  = smem + SM_RED;

    const int tid  = threadIdx.x;
    const int w    = tid >> 5;      // 0..7
    const int lane = tid & 31;

    for (int grp = blockIdx.x; grp < NITER; grp += gridDim.x) {
        const int flat = grp*PPI + w;          // this warp's point
        const int n = flat >> 13;

        // ---------------- Phase A: geometry (lane = neighbor a) ----------------
        const int nb_idx = flat*ANB + lane;
        const int j   = nbrs[nb_idx];
        const float msk = rmask[nb_idx];
        const float* cc = coords + (long)flat*3;
        const float c0x = cc[0], c0y = cc[1], c0z = cc[2];
        const float* cj = coords + ((long)(n*BPTS + j))*3;
        const float dx = cj[0]-c0x, dy = cj[1]-c0y, dz = cj[2]-c0z;
        const float r2 = dx*dx + dy*dy + dz*dz;
        const float r  = sqrtf(r2);
        const float inv = __fdividef(1.0f, r + 1e-8f);
        const float ux = dx*inv, uy = dy*inv, uz = dz*inv;
        const float y0 = 0.28209479f;
        const float y1 = 0.48860251f*ux, y2 = 0.48860251f*uy, y3 = 0.48860251f*uz;
        const float y4 = 1.09254843f*ux*uy, y5 = 1.09254843f*uy*uz;
        const float y6 = 0.31539157f*(3.0f*uz*uz - 1.0f);
        const float y7 = 1.09254843f*ux*uz;
        const float y8 = 0.54627421f*(ux*ux - uy*uy);
        float rb[4];
        #pragma unroll
        for (int i = 0; i < 4; i++){
            float tt = (r - 0.5f*(float)(i+1)) * 2.0f;
            rb[i] = msk * __expf(-tt*tt);      // mask folded into radial basis
        }
        // geom row: [0..3]=rb quad, [4..11]=y0..y7, [12]=y8 (13 unique floats)
        float* grow = geomS + (w*32 + lane)*GSTRIDE;
        sts128(grow + 0, pack2(rb[0], rb[1]), pack2(rb[2], rb[3]));
        sts128(grow + 4, pack2(y0, y1), pack2(y2, y3));
        sts128(grow + 8, pack2(y4, y5), pack2(y6, y7));
        grow[12] = y8;
        __syncwarp();

        // ---------------- Phase A: M accumulation, feat prefetch depth 8 ----------------
        const float* inrow = g_inputT + (((long)n << 13) * CIN) + lane;
        float fp[8];
        #pragma unroll
        for (int q = 0; q < 8; q++){
            int jq = __shfl_sync(0xffffffffu, j, q);
            fp[q] = __ldg(inrow + (long)jq*CIN);
        }
        unsigned long long M01[9], M23[9];
        #pragma unroll
        for (int s = 0; s < 9; s++){ M01[s] = 0ull; M23[s] = 0ull; }

        #pragma unroll
        for (int a8 = 0; a8 < 32; a8 += 8){
            #pragma unroll
            for (int q = 0; q < 8; q++){
                const int a = a8 + q;
                const float* g = geomS + (w*32 + a)*GSTRIDE;
                unsigned long long rb01, rb23;
                lds128(g + 0, rb01, rb23);
                const float4 ya = *(const float4*)(g + 4);
                const float4 yb = *(const float4*)(g + 8);
                const float  yc = g[12];
                const float f = fp[q];
                if (a8 + 8 < 32){
                    int jn = __shfl_sync(0xffffffffu, j, a + 8);
                    fp[q] = __ldg(inrow + (long)jn*CIN);
                }
                unsigned long long f2 = pack2(f, f);
                unsigned long long frb01 = mul2(f2, rb01);
                unsigned long long frb23 = mul2(f2, rb23);
                unsigned long long yd[9];
                yd[0] = pack2(ya.x, ya.x); yd[1] = pack2(ya.y, ya.y);
                yd[2] = pack2(ya.z, ya.z); yd[3] = pack2(ya.w, ya.w);
                yd[4] = pack2(yb.x, yb.x); yd[5] = pack2(yb.y, yb.y);
                yd[6] = pack2(yb.z, yb.z); yd[7] = pack2(yb.w, yb.w);
                yd[8] = pack2(yc, yc);
                #pragma unroll
                for (int s = 0; s < 9; s++){
                    M01[s] = fma2(frb01, yd[s], M01[s]);
                    M23[s] = fma2(frb23, yd[s], M23[s]);
                }
            }
        }
        // write M to smem: Msh[p=w][c*36 + s*4 + r]
        {
            float* mrow = MshS + w*1152 + lane*36;
            #pragma unroll
            for (int s = 0; s < 9; s++)
                sts128(mrow + s*4, M01[s], M23[s]);
        }
        __syncthreads();

        // ---------------- Phase B: W contraction ----------------
        // warp w owns g in [w*36, w*36+36); lane = d; W rows via LDG (L2), prefetch depth 2
        unsigned long long acc[PPI];
        #pragma unroll
        for (int p = 0; p < PPI; p++) acc[p] = 0ull;
        const int g0 = w*36;
        const ulonglong2* wrow = (const ulonglong2*)(g_wperm + ((long)g0*32 + lane)*4);
        ulonglong2 wv0 = __ldg(wrow);
        ulonglong2 wv1 = __ldg(wrow + 32);
        #pragma unroll
        for (int gi = 0; gi < 36; gi++){
            const ulonglong2 wc = (gi & 1) ? wv1 : wv0;
            if (gi + 2 < 36){
                if (gi & 1) wv1 = __ldg(wrow + (gi+2)*32);
                else        wv0 = __ldg(wrow + (gi+2)*32);
            }
            const float* mbase = MshS + (g0 + gi)*4;
            unsigned long long m0[PPI], m1[PPI];
            #pragma unroll
            for (int p = 0; p < PPI; p++) lds128(mbase + p*1152, m0[p], m1[p]);
            #pragma unroll
            for (int p = 0; p < PPI; p++){
                acc[p] = fma2(m0[p], wc.x, acc[p]);
                acc[p] = fma2(m1[p], wc.y, acc[p]);
            }
        }
        #pragma unroll
        for (int p = 0; p < PPI; p++){
            float lo, hi; unpack2(acc[p], lo, hi);
            redS[(w*PPI + p)*RED_STRIDE + lane] = lo + hi;   // red[w][p][d]
        }
        __syncthreads();

        // ---------------- final cross-warp reduce + store ----------------
        {
            const int d = tid >> 3;      // 0..31
            const int p = tid & 7;       // 0..7
            float s = 0.f;
            #pragma unroll
            for (int ww = 0; ww < WARPS; ww++)
                s += redS[(ww*PPI + p)*RED_STRIDE + d];
            const int flatp = grp*PPI + p;
            const int nn = flatp >> 13;
            const int bb = flatp & (BPTS-1);
            out[((long)(nn*DOUT + d))*BPTS + bb] = s;
        }
        // 2 barriers/iter: Msh reads done before sync#2; red reads (reduce)
        // done before the next iteration's sync#1, which precedes red writes.
    }
}

// ---------------- launch ----------------
extern "C" void kernel_launch(void* const* d_in, const int* in_sizes, int n_in,
                              void* d_out, int out_size)
{
    const float* input  = (const float*)d_in[0];
    const float* coords = (const float*)d_in[1];
    const float* rmask  = (const float*)d_in[2];
    const float* W      = (const float*)d_in[3];
    const int*   nbrs   = (const int*)d_in[4];
    float* out = (float*)d_out;

    (void)in_sizes; (void)n_in; (void)out_size;

    // fused prep: transpose input + permute W (1024 + 144 blocks)
    prep_all<<<1168, 256>>>(input, W);

    // main: persistent CTAs, two per SM
    int dev = 0; cudaGetDevice(&dev);
    int smcount = 148;
    cudaDeviceGetAttribute(&smcount, cudaDevAttrMultiProcessorCount, dev);

    size_t shmem = (size_t)SM_FLOATS * sizeof(float);  // 65792 B
    cudaFuncSetAttribute(se3_main, cudaFuncAttributeMaxDynamicSharedMemorySize, (int)shmem);
    se3_main<<<2*smcount, THREADS, shmem>>>(coords, rmask, nbrs, out);
}

// round 6
// speedup vs baseline: 1.2702x; 1.0781x over previous
#include <cuda_runtime.h>

#define NN 4
#define BPTS 8192
#define CIN 32
#define DOUT 32
#define ANB 32
#define NBAS 36
#define TOTAL 32768
#define PPI 32
#define THREADS 512
#define WARPS 16
#define NITER (TOTAL/PPI)
#define KK 1152
#define KPW 72
#define MPS 33
#define GSTRIDE 20

typedef unsigned long long u64;

__device__ float g_inputT[NN*BPTS*CIN];   // (n,b,c)
__device__ float g_wlin[KK*32];           // [kk][d], kk=(s*4+r)*32+c

// ---------------- f32x2 helpers ----------------
__device__ __forceinline__ u64 pack2(float x, float y){
    u64 r; asm("mov.b64 %0,{%1,%2};" : "=l"(r) : "f"(x), "f"(y)); return r;
}
__device__ __forceinline__ void unpack2(u64 v, float& x, float& y){
    asm("mov.b64 {%0,%1},%2;" : "=f"(x), "=f"(y) : "l"(v));
}
__device__ __forceinline__ u64 fma2(u64 a, u64 b, u64 c){
    u64 d; asm("fma.rn.f32x2 %0,%1,%2,%3;" : "=l"(d) : "l"(a), "l"(b), "l"(c)); return d;
}
__device__ __forceinline__ u64 add2(u64 a, u64 b){
    u64 d; asm("add.rn.f32x2 %0,%1,%2;" : "=l"(d) : "l"(a), "l"(b)); return d;
}
__device__ __forceinline__ u64 mul2(u64 a, u64 b){
    u64 d; asm("mul.rn.f32x2 %0,%1,%2;" : "=l"(d) : "l"(a), "l"(b)); return d;
}
__device__ __forceinline__ void lds128(const float* p, u64& a, u64& b){
    unsigned s = (unsigned)__cvta_generic_to_shared(p);
    asm volatile("ld.shared.v2.u64 {%0,%1},[%2];" : "=l"(a), "=l"(b) : "r"(s));
}
__device__ __forceinline__ void sts128(float* p, u64 a, u64 b){
    unsigned s = (unsigned)__cvta_generic_to_shared(p);
    asm volatile("st.shared.v2.u64 [%0],{%1,%2};" :: "r"(s), "l"(a), "l"(b));
}
__device__ __forceinline__ float lds32(const float* p){
    float v; unsigned s = (unsigned)__cvta_generic_to_shared(p);
    asm volatile("ld.shared.f32 %0,[%1];" : "=f"(v) : "r"(s)); return v;
}
__device__ __forceinline__ void sts32(float* p, float v){
    unsigned s = (unsigned)__cvta_generic_to_shared(p);
    asm volatile("st.shared.f32 [%0],%1;" :: "r"(s), "f"(v));
}
__device__ __forceinline__ u64 lds64(const float* p){
    u64 v; unsigned s = (unsigned)__cvta_generic_to_shared(p);
    asm volatile("ld.shared.b64 %0,[%1];" : "=l"(v) : "r"(s)); return v;
}
__device__ __forceinline__ void sts64(float* p, u64 v){
    unsigned s = (unsigned)__cvta_generic_to_shared(p);
    asm volatile("st.shared.b64 [%0],%1;" :: "r"(s), "l"(v));
}

// ---------------- fused prep ----------------
__global__ void prep_all(const float* __restrict__ in, const float* __restrict__ W){
    const int bx = blockIdx.x;
    const int tid = threadIdx.x;           // 256
    if (bx < 1024){
        __shared__ float t[32][33];
        const int n  = bx >> 8;
        const int b0 = (bx & 255) * 32;
        const int tx = tid & 31, ty = tid >> 5;
        #pragma unroll
        for (int i = ty; i < 32; i += 8)
            t[i][tx] = in[(n*CIN + i)*BPTS + b0 + tx];
        __syncthreads();
        #pragma unroll
        for (int i = ty; i < 32; i += 8)
            g_inputT[(n*BPTS + b0 + i)*CIN + tx] = t[tx][i];
    } else {
        int t = (bx - 1024)*256 + tid;
        if (t < KK*32){
            int d  = t & 31;
            int kk = t >> 5;
            int c   = kk & 31;
            int s4r = kk >> 5;
            int r = s4r & 3, s = s4r >> 2;
            g_wlin[t] = W[(d*CIN + c)*NBAS + r*9 + s];
        }
    }
}

// ---------------- main ----------------
// smem floats: geomS 16*32*20 = 10240 | Mp KK*33 = 38016  -> 193024 bytes
// redd (16ks * 32d * 34p = 17408 floats) ALIASES Mp (barrier-ordered).
#define SM_GEOM 0
#define SM_MP   (WARPS*32*GSTRIDE)
#define SM_FLOATS (SM_MP + KK*MPS)

__global__ void __launch_bounds__(THREADS, 1)
se3_main(const float* __restrict__ coords,
         const float* __restrict__ rmask,
         const int*   __restrict__ nbrs,
         float*       __restrict__ out)
{
    extern __shared__ float smem[];
    float* geomS = smem + SM_GEOM;
    float* Mp    = smem + SM_MP;
    float* redd  = Mp;                      // alias, barrier-ordered

    const int tid  = threadIdx.x;
    const int w    = tid >> 5;              // 0..15
    const int lane = tid & 31;
    const int pg   = lane & 7;              // p-chunk 0..7 (4 p each)
    const int dg   = lane >> 3;             // d-group 0..3 (8 d each)

    for (int grp = blockIdx.x; grp < NITER; grp += gridDim.x) {
        const int flatbase = grp*PPI;
        const int n   = flatbase >> 13;
        const int bb0 = flatbase & (BPTS-1);

        // ================= Phase A: 2 points per warp =================
        #pragma unroll 1
        for (int sub = 0; sub < 2; sub++){
            const int p = w*2 + sub;
            const int flat = flatbase + p;

            // geometry, lane = neighbor a
            const int nb_idx = flat*ANB + lane;
            const int jn  = nbrs[nb_idx];
            const float msk = rmask[nb_idx];
            const float* cc = coords + (long)flat*3;
            const float c0x = cc[0], c0y = cc[1], c0z = cc[2];
            const float* cj = coords + ((long)(n*BPTS + jn))*3;
            const float dx = cj[0]-c0x, dy = cj[1]-c0y, dz = cj[2]-c0z;
            const float r  = sqrtf(dx*dx + dy*dy + dz*dz);
            const float inv = __fdividef(1.0f, r + 1e-8f);
            const float ux = dx*inv, uy = dy*inv, uz = dz*inv;
            const float y0 = 0.28209479f;
            const float y1 = 0.48860251f*ux, y2 = 0.48860251f*uy, y3 = 0.48860251f*uz;
            const float y4 = 1.09254843f*ux*uy, y5 = 1.09254843f*uy*uz;
            const float y6 = 0.31539157f*(3.0f*uz*uz - 1.0f);
            const float y7 = 1.09254843f*ux*uz;
            const float y8 = 0.54627421f*(ux*ux - uy*uy);
            float rb0, rb1, rb2, rb3;
            {
                float t0 = (r - 0.5f)*2.0f, t1 = (r - 1.0f)*2.0f;
                float t2 = (r - 1.5f)*2.0f, t3 = (r - 2.0f)*2.0f;
                rb0 = msk*__expf(-t0*t0); rb1 = msk*__expf(-t1*t1);
                rb2 = msk*__expf(-t2*t2); rb3 = msk*__expf(-t3*t3);
            }
            float* grow = geomS + (w*32 + lane)*GSTRIDE;
            sts128(grow + 0, pack2(rb0, rb1), pack2(rb2, rb3));
            sts128(grow + 4, pack2(y0, y1), pack2(y2, y3));
            sts128(grow + 8, pack2(y4, y5), pack2(y6, y7));
            sts32(grow + 12, y8);
            __syncwarp();

            // feature gather (lane = channel c), prefetch depth 8
            const float* inrow = g_inputT + (((long)n << 13) * CIN) + lane;
            float fp[8];
            #pragma unroll
            for (int q = 0; q < 8; q++){
                int jq = __shfl_sync(0xffffffffu, jn, q);
                fp[q] = __ldg(inrow + (long)jq*CIN);
            }
            u64 M01[9], M23[9];
            #pragma unroll
            for (int s = 0; s < 9; s++){ M01[s] = 0ull; M23[s] = 0ull; }

            #pragma unroll
            for (int a8 = 0; a8 < 32; a8 += 8){
                #pragma unroll
                for (int q = 0; q < 8; q++){
                    const int a = a8 + q;
                    const float* g = geomS + (w*32 + a)*GSTRIDE;
                    u64 rb01, rb23;
                    lds128(g + 0, rb01, rb23);
                    const float4 ya = *(const float4*)(g + 4);
                    const float4 yb = *(const float4*)(g + 8);
                    const float  yc = lds32(g + 12);
                    const float f = fp[q];
                    if (a8 + 8 < 32){
                        int jq = __shfl_sync(0xffffffffu, jn, a + 8);
                        fp[q] = __ldg(inrow + (long)jq*CIN);
                    }
                    u64 f2 = pack2(f, f);
                    u64 frb01 = mul2(f2, rb01);
                    u64 frb23 = mul2(f2, rb23);
                    u64 yd[9];
                    yd[0]=pack2(ya.x,ya.x); yd[1]=pack2(ya.y,ya.y);
                    yd[2]=pack2(ya.z,ya.z); yd[3]=pack2(ya.w,ya.w);
                    yd[4]=pack2(yb.x,yb.x); yd[5]=pack2(yb.y,yb.y);
                    yd[6]=pack2(yb.z,yb.z); yd[7]=pack2(yb.w,yb.w);
                    yd[8]=pack2(yc,yc);
                    #pragma unroll
                    for (int s = 0; s < 9; s++){
                        M01[s] = fma2(frb01, yd[s], M01[s]);
                        M23[s] = fma2(frb23, yd[s], M23[s]);
                    }
                }
            }
            // Mp[kk][p], kk=(s*4+r)*32+c : conflict-free scalar stores (lane*33 == lane mod 32)
            #pragma unroll
            for (int s = 0; s < 9; s++){
                float a0,a1,a2,a3;
                unpack2(M01[s], a0, a1);
                unpack2(M23[s], a2, a3);
                float* base = Mp + ((s*4)*32 + lane)*MPS + p;
                sts32(base + 0*32*MPS, a0);
                sts32(base + 1*32*MPS, a1);
                sts32(base + 2*32*MPS, a2);
                sts32(base + 3*32*MPS, a3);
            }
            __syncwarp();
        }
        __syncthreads();   // Mp complete

        // ================= Phase B: k-split register-tiled GEMM =================
        // warp = k-slice [w*72, w*72+72); thread = 4p (pg) x 8d (dg)
        u64 acc[2][8];
        #pragma unroll
        for (int a = 0; a < 2; a++)
            #pragma unroll
            for (int b = 0; b < 8; b++) acc[a][b] = 0ull;

        const int kb = w*KPW;
        const float4* wq = ((const float4*)g_wlin) + dg*2;  // + k*8 (+1 for hi half)
        float4 cA0 = __ldg(wq + (long)(kb+0)*8), cA1 = __ldg(wq + (long)(kb+0)*8 + 1);
        float4 cB0 = __ldg(wq + (long)(kb+1)*8), cB1 = __ldg(wq + (long)(kb+1)*8 + 1);

        #pragma unroll 2
        for (int t = 0; t < KPW/2; t++){
            const int k0 = kb + t*2;
            float4 nA0, nA1, nB0, nB1;
            if (t + 1 < KPW/2){
                nA0 = __ldg(wq + (long)(k0+2)*8); nA1 = __ldg(wq + (long)(k0+2)*8 + 1);
                nB0 = __ldg(wq + (long)(k0+3)*8); nB1 = __ldg(wq + (long)(k0+3)*8 + 1);
            }
            #pragma unroll
            for (int kt = 0; kt < 2; kt++){
                const int j = (kt + dg) & 1;          // staggered k-row: conflict-free LDS
                const float* mr = Mp + (k0 + j)*MPS + pg*4;
                float m0 = lds32(mr+0), m1 = lds32(mr+1);
                float m2 = lds32(mr+2), m3 = lds32(mr+3);
                u64 m01 = pack2(m0, m1), m23 = pack2(m2, m3);
                float4 wa = j ? cB0 : cA0;
                float4 wb = j ? cB1 : cA1;
                u64 s0 = pack2(wa.x,wa.x), s1 = pack2(wa.y,wa.y);
                u64 s2 = pack2(wa.z,wa.z), s3 = pack2(wa.w,wa.w);
                u64 s4 = pack2(wb.x,wb.x), s5 = pack2(wb.y,wb.y);
                u64 s6 = pack2(wb.z,wb.z), s7 = pack2(wb.w,wb.w);
                acc[0][0]=fma2(m01,s0,acc[0][0]); acc[1][0]=fma2(m23,s0,acc[1][0]);
                acc[0][1]=fma2(m01,s1,acc[0][1]); acc[1][1]=fma2(m23,s1,acc[1][1]);
                acc[0][2]=fma2(m01,s2,acc[0][2]); acc[1][2]=fma2(m23,s2,acc[1][2]);
                acc[0][3]=fma2(m01,s3,acc[0][3]); acc[1][3]=fma2(m23,s3,acc[1][3]);
                acc[0][4]=fma2(m01,s4,acc[0][4]); acc[1][4]=fma2(m23,s4,acc[1][4]);
                acc[0][5]=fma2(m01,s5,acc[0][5]); acc[1][5]=fma2(m23,s5,acc[1][5]);
                acc[0][6]=fma2(m01,s6,acc[0][6]); acc[1][6]=fma2(m23,s6,acc[1][6]);
                acc[0][7]=fma2(m01,s7,acc[0][7]); acc[1][7]=fma2(m23,s7,acc[1][7]);
            }
            cA0 = nA0; cA1 = nA1; cB0 = nB0; cB1 = nB1;
        }
        __syncthreads();   // all Mp reads done before redd (alias) writes

        // write k-partials: redd[ks=w][d][p] word = w*1088 + d*34 + p
        {
            float* rbse = redd + w*1088 + (dg*8)*34 + pg*4;
            #pragma unroll
            for (int dd = 0; dd < 8; dd++){
                sts64(rbse + dd*34 + 0, acc[0][dd]);
                sts64(rbse + dd*34 + 2, acc[1][dd]);
            }
        }
        __syncthreads();

        // reduce 16 partials: thread -> (d = tid>>4, p-pair = tid&15)
        {
            const int d  = tid >> 4;
            const int pp = tid & 15;
            const float* rb = redd + d*34 + pp*2;
            u64 s = lds64(rb);
            #pragma unroll
            for (int ks = 1; ks < 16; ks++)
                s = add2(s, lds64(rb + ks*1088));
            float lo, hi; unpack2(s, lo, hi);
            float* o = out + ((long)(n*DOUT + d))*BPTS + bb0 + pp*2;
            o[0] = lo; o[1] = hi;
        }
        __syncthreads();   // protect redd (=Mp) before next iter's Phase A
    }
}

// ---------------- launch ----------------
extern "C" void kernel_launch(void* const* d_in, const int* in_sizes, int n_in,
                              void* d_out, int out_size)
{
    const float* input  = (const float*)d_in[0];
    const float* coords = (const float*)d_in[1];
    const float* rmask  = (const float*)d_in[2];
    const float* W      = (const float*)d_in[3];
    const int*   nbrs   = (const int*)d_in[4];
    float* out = (float*)d_out;

    (void)in_sizes; (void)n_in; (void)out_size;

    prep_all<<<1168, 256>>>(input, W);

    int dev = 0; cudaGetDevice(&dev);
    int smcount = 148;
    cudaDeviceGetAttribute(&smcount, cudaDevAttrMultiProcessorCount, dev);

    size_t shmem = (size_t)SM_FLOATS * sizeof(float);   // 193024 B
    cudaFuncSetAttribute(se3_main, cudaFuncAttributeMaxDynamicSharedMemorySize, (int)shmem);
    se3_main<<<smcount, THREADS, shmem>>>(coords, rmask, nbrs, out);
}

// round 7
// speedup vs baseline: 1.2915x; 1.0168x over previous
#include <cuda_runtime.h>

#define NN 4
#define BPTS 8192
#define CIN 32
#define DOUT 32
#define ANB 32
#define NBAS 36
#define TOTAL 32768
#define PPI 32
#define THREADS 512
#define WARPS 16
#define NITER (TOTAL/PPI)
#define KK 1152
#define KPW 72
#define MPS 33

typedef unsigned long long u64;

__device__ float g_inputT[NN*BPTS*CIN];   // (n,b,c)
__device__ float g_wlin[KK*32];           // [kk][d], kk=(s*4+r)*32+c

// ---------------- f32x2 helpers ----------------
__device__ __forceinline__ u64 pack2(float x, float y){
    u64 r; asm("mov.b64 %0,{%1,%2};" : "=l"(r) : "f"(x), "f"(y)); return r;
}
__device__ __forceinline__ void unpack2(u64 v, float& x, float& y){
    asm("mov.b64 {%0,%1},%2;" : "=f"(x), "=f"(y) : "l"(v));
}
__device__ __forceinline__ u64 fma2(u64 a, u64 b, u64 c){
    u64 d; asm("fma.rn.f32x2 %0,%1,%2,%3;" : "=l"(d) : "l"(a), "l"(b), "l"(c)); return d;
}
__device__ __forceinline__ u64 add2(u64 a, u64 b){
    u64 d; asm("add.rn.f32x2 %0,%1,%2;" : "=l"(d) : "l"(a), "l"(b)); return d;
}
__device__ __forceinline__ u64 mul2(u64 a, u64 b){
    u64 d; asm("mul.rn.f32x2 %0,%1,%2;" : "=l"(d) : "l"(a), "l"(b)); return d;
}
__device__ __forceinline__ float lds32(const float* p){
    float v; unsigned s = (unsigned)__cvta_generic_to_shared(p);
    asm volatile("ld.shared.f32 %0,[%1];" : "=f"(v) : "r"(s)); return v;
}
__device__ __forceinline__ void sts32(float* p, float v){
    unsigned s = (unsigned)__cvta_generic_to_shared(p);
    asm volatile("st.shared.f32 [%0],%1;" :: "r"(s), "f"(v));
}
__device__ __forceinline__ u64 lds64(const void* p){
    u64 v; unsigned s = (unsigned)__cvta_generic_to_shared(p);
    asm volatile("ld.shared.b64 %0,[%1];" : "=l"(v) : "r"(s)); return v;
}
__device__ __forceinline__ void sts64(void* p, u64 v){
    unsigned s = (unsigned)__cvta_generic_to_shared(p);
    asm volatile("st.shared.b64 [%0],%1;" :: "r"(s), "l"(v));
}

// ---------------- fused prep ----------------
__global__ void prep_all(const float* __restrict__ in, const float* __restrict__ W){
    const int bx = blockIdx.x;
    const int tid = threadIdx.x;           // 256
    if (bx < 1024){
        __shared__ float t[32][33];
        const int n  = bx >> 8;
        const int b0 = (bx & 255) * 32;
        const int tx = tid & 31, ty = tid >> 5;
        #pragma unroll
        for (int i = ty; i < 32; i += 8)
            t[i][tx] = in[(n*CIN + i)*BPTS + b0 + tx];
        __syncthreads();
        #pragma unroll
        for (int i = ty; i < 32; i += 8)
            g_inputT[(n*BPTS + b0 + i)*CIN + tx] = t[tx][i];
    } else {
        int t = (bx - 1024)*256 + tid;
        if (t < KK*32){
            int d  = t & 31;
            int kk = t >> 5;
            int c   = kk & 31;
            int s4r = kk >> 5;
            int r = s4r & 3, s = s4r >> 2;
            g_wlin[t] = W[(d*CIN + c)*NBAS + r*9 + s];
        }
    }
}

// ---------------- main ----------------
// smem floats:
//   geomP  : 6 u64-fields x 512 rows = 6144 f     (SoA pairs: rb01,rb23,y01,y23,y45,y67)
//   geomY8 : 512 f
//   Mp     : KK*33 = 38016 f
// total 44672 f = 178688 B. redd (16*32*17 u64 = 69632B) ALIASES Mp (barrier-ordered).
#define SM_GP   0
#define SM_Y8   6144
#define SM_MP   (6144 + 512)
#define SM_FLOATS (SM_MP + KK*MPS)

__global__ void __launch_bounds__(THREADS, 1)
se3_main(const float* __restrict__ coords,
         const float* __restrict__ rmask,
         const int*   __restrict__ nbrs,
         float*       __restrict__ out)
{
    extern __shared__ float smem[];
    u64*   geomP = (u64*)(smem + SM_GP);     // [q*512 + row]
    float* geomY8 = smem + SM_Y8;            // [row]
    float* Mp    = smem + SM_MP;             // [kk*33 + p]
    u64*   redd  = (u64*)Mp;                 // alias, barrier-ordered

    const int tid  = threadIdx.x;
    const int w    = tid >> 5;               // 0..15
    const int lane = tid & 31;
    const int pg   = lane & 7;               // p-chunk (4 p each)
    const int dg   = lane >> 3;              // d-group (8 d each)

    for (int grp = blockIdx.x; grp < NITER; grp += gridDim.x) {
        const int flatbase = grp*PPI;
        const int n   = flatbase >> 13;
        const int bb0 = flatbase & (BPTS-1);

        // ================= Phase A: 2 points per warp =================
        #pragma unroll 1
        for (int sub = 0; sub < 2; sub++){
            const int p = w*2 + sub;
            const int flat = flatbase + p;

            // geometry, lane = neighbor a
            const int nb_idx = flat*ANB + lane;
            const int jn  = nbrs[nb_idx];
            const float msk = rmask[nb_idx];
            const float* cc = coords + (long)flat*3;
            const float c0x = cc[0], c0y = cc[1], c0z = cc[2];
            const float* cj = coords + ((long)(n*BPTS + jn))*3;
            const float dx = cj[0]-c0x, dy = cj[1]-c0y, dz = cj[2]-c0z;
            const float r  = sqrtf(dx*dx + dy*dy + dz*dz);
            const float inv = __fdividef(1.0f, r + 1e-8f);
            const float ux = dx*inv, uy = dy*inv, uz = dz*inv;
            const float y0 = 0.28209479f;
            const float y1 = 0.48860251f*ux, y2 = 0.48860251f*uy, y3 = 0.48860251f*uz;
            const float y4 = 1.09254843f*ux*uy, y5 = 1.09254843f*uy*uz;
            const float y6 = 0.31539157f*(3.0f*uz*uz - 1.0f);
            const float y7 = 1.09254843f*ux*uz;
            const float y8 = 0.54627421f*(ux*ux - uy*uy);
            float rb0, rb1, rb2, rb3;
            {
                float t0 = (r - 0.5f)*2.0f, t1 = (r - 1.0f)*2.0f;
                float t2 = (r - 1.5f)*2.0f, t3 = (r - 2.0f)*2.0f;
                rb0 = msk*__expf(-t0*t0); rb1 = msk*__expf(-t1*t1);
                rb2 = msk*__expf(-t2*t2); rb3 = msk*__expf(-t3*t3);
            }
            // SoA pair stores: lane-distinct stride-1 => conflict-free
            const int row = w*32 + lane;
            sts64(geomP + 0*512 + row, pack2(rb0, rb1));
            sts64(geomP + 1*512 + row, pack2(rb2, rb3));
            sts64(geomP + 2*512 + row, pack2(y0, y1));
            sts64(geomP + 3*512 + row, pack2(y2, y3));
            sts64(geomP + 4*512 + row, pack2(y4, y5));
            sts64(geomP + 5*512 + row, pack2(y6, y7));
            sts32(geomY8 + row, y8);
            __syncwarp();

            // feature gather (lane = channel c), prefetch depth 8
            const float* inrow = g_inputT + (((long)n << 13) * CIN) + lane;
            float fp[8];
            #pragma unroll
            for (int q = 0; q < 8; q++){
                int jq = __shfl_sync(0xffffffffu, jn, q);
                fp[q] = __ldg(inrow + (long)jq*CIN);
            }
            u64 M01[9], M23[9];
            #pragma unroll
            for (int s = 0; s < 9; s++){ M01[s] = 0ull; M23[s] = 0ull; }

            #pragma unroll
            for (int a8 = 0; a8 < 32; a8 += 8){
                #pragma unroll
                for (int q = 0; q < 8; q++){
                    const int a = a8 + q;
                    const int row2 = w*32 + a;
                    u64 rb01 = lds64(geomP + 0*512 + row2);
                    u64 rb23 = lds64(geomP + 1*512 + row2);
                    u64 y01  = lds64(geomP + 2*512 + row2);
                    u64 y23  = lds64(geomP + 3*512 + row2);
                    u64 y45  = lds64(geomP + 4*512 + row2);
                    u64 y67  = lds64(geomP + 5*512 + row2);
                    float y8v = lds32(geomY8 + row2);
                    const float f = fp[q];
                    if (a8 + 8 < 32){
                        int jq = __shfl_sync(0xffffffffu, jn, a + 8);
                        fp[q] = __ldg(inrow + (long)jq*CIN);
                    }
                    u64 f2 = pack2(f, f);
                    u64 frb01 = mul2(f2, rb01);
                    u64 frb23 = mul2(f2, rb23);
                    float t0,t1,t2,t3,t4,t5,t6,t7;
                    unpack2(y01, t0, t1); unpack2(y23, t2, t3);
                    unpack2(y45, t4, t5); unpack2(y67, t6, t7);
                    u64 yd[9];
                    yd[0]=pack2(t0,t0); yd[1]=pack2(t1,t1); yd[2]=pack2(t2,t2);
                    yd[3]=pack2(t3,t3); yd[4]=pack2(t4,t4); yd[5]=pack2(t5,t5);
                    yd[6]=pack2(t6,t6); yd[7]=pack2(t7,t7); yd[8]=pack2(y8v,y8v);
                    #pragma unroll
                    for (int s = 0; s < 9; s++){
                        M01[s] = fma2(frb01, yd[s], M01[s]);
                        M23[s] = fma2(frb23, yd[s], M23[s]);
                    }
                }
            }
            // Mp[kk][p], kk=(s*4+r)*32+c : conflict-free scalar stores
            #pragma unroll
            for (int s = 0; s < 9; s++){
                float a0,a1,a2,a3;
                unpack2(M01[s], a0, a1);
                unpack2(M23[s], a2, a3);
                float* base = Mp + ((s*4)*32 + lane)*MPS + p;
                sts32(base + 0*32*MPS, a0);
                sts32(base + 1*32*MPS, a1);
                sts32(base + 2*32*MPS, a2);
                sts32(base + 3*32*MPS, a3);
            }
            __syncwarp();
        }
        __syncthreads();   // Mp complete

        // ================= Phase B: k-split GEMM, d-paired =================
        // warp = k-slice [w*72, +72); thread = 4p (pg) x 8d (dg, 4 d-pairs)
        u64 acc[4][4];     // [pi][dd]  d-pair = (dg*8+dd*2, +1)
        #pragma unroll
        for (int a = 0; a < 4; a++)
            #pragma unroll
            for (int b = 0; b < 4; b++) acc[a][b] = 0ull;

        const int kb = w*KPW;
        const ulonglong2* wq = ((const ulonglong2*)g_wlin) + dg*2;  // + k*8 (+1)
        // prefetch depth 3 (covers L2 latency)
        ulonglong2 pf0[3], pf1[3];
        #pragma unroll
        for (int i = 0; i < 3; i++){
            pf0[i] = __ldg(wq + (long)(kb+i)*8);
            pf1[i] = __ldg(wq + (long)(kb+i)*8 + 1);
        }
        #pragma unroll 3
        for (int kk = 0; kk < KPW; kk++){
            const int k = kb + kk;
            const int slot = kk % 3;
            const ulonglong2 wa = pf0[slot];
            const ulonglong2 wb = pf1[slot];
            if (kk + 3 < KPW){
                pf0[slot] = __ldg(wq + (long)(k+3)*8);
                pf1[slot] = __ldg(wq + (long)(k+3)*8 + 1);
            }
            const float* mr = Mp + k*MPS + pg*4;
            float m0 = lds32(mr+0), m1 = lds32(mr+1);
            float m2 = lds32(mr+2), m3 = lds32(mr+3);
            u64 md0 = pack2(m0,m0), md1 = pack2(m1,m1);
            u64 md2 = pack2(m2,m2), md3 = pack2(m3,m3);
            acc[0][0]=fma2(md0, wa.x, acc[0][0]);
            acc[0][1]=fma2(md0, wa.y, acc[0][1]);
            acc[0][2]=fma2(md0, wb.x, acc[0][2]);
            acc[0][3]=fma2(md0, wb.y, acc[0][3]);
            acc[1][0]=fma2(md1, wa.x, acc[1][0]);
            acc[1][1]=fma2(md1, wa.y, acc[1][1]);
            acc[1][2]=fma2(md1, wb.x, acc[1][2]);
            acc[1][3]=fma2(md1, wb.y, acc[1][3]);
            acc[2][0]=fma2(md2, wa.x, acc[2][0]);
            acc[2][1]=fma2(md2, wa.y, acc[2][1]);
            acc[2][2]=fma2(md2, wb.x, acc[2][2]);
            acc[2][3]=fma2(md2, wb.y, acc[2][3]);
            acc[3][0]=fma2(md3, wa.x, acc[3][0]);
            acc[3][1]=fma2(md3, wa.y, acc[3][1]);
            acc[3][2]=fma2(md3, wb.x, acc[3][2]);
            acc[3][3]=fma2(md3, wb.y, acc[3][3]);
        }
        __syncthreads();   // all Mp reads done before redd (alias) writes

        // partial store: per-thread slot, pad 17 u64 -> conflict-free
        {
            u64* slotp = redd + (u64)(w*32 + lane)*17;
            #pragma unroll
            for (int pi = 0; pi < 4; pi++)
                #pragma unroll
                for (int dd = 0; dd < 4; dd++)
                    sts64(slotp + pi*4 + dd, acc[pi][dd]);
        }
        __syncthreads();

        // reduce 16 k-slices; reducer (rw = pi*4+dd, rl = producer lane)
        {
            const int rw = tid >> 5;           // 0..15 = pi*4+dd
            const int rl = tid & 31;           // producer lane
            const int pi = rw >> 2, dd = rw & 3;
            const int dgp = rl >> 3, pgp = rl & 7;
            const u64* base = redd + rl*17 + rw;
            u64 s = lds64(base);
            #pragma unroll
            for (int ks = 1; ks < 16; ks++)
                s = add2(s, lds64(base + ks*544));
            float lo, hi; unpack2(s, lo, hi);
            const int p = pgp*4 + pi;
            const int d = dgp*8 + dd*2;
            float* o = out + ((long)(n*DOUT + d))*BPTS + bb0 + p;
            o[0]    = lo;
            o[BPTS] = hi;
        }
        __syncthreads();   // protect redd (=Mp) before next iter's Phase A
    }
}

// ---------------- launch ----------------
extern "C" void kernel_launch(void* const* d_in, const int* in_sizes, int n_in,
                              void* d_out, int out_size)
{
    const float* input  = (const float*)d_in[0];
    const float* coords = (const float*)d_in[1];
    const float* rmask  = (const float*)d_in[2];
    const float* W      = (const float*)d_in[3];
    const int*   nbrs   = (const int*)d_in[4];
    float* out = (float*)d_out;

    (void)in_sizes; (void)n_in; (void)out_size;

    prep_all<<<1168, 256>>>(input, W);

    int dev = 0; cudaGetDevice(&dev);
    int smcount = 148;
    cudaDeviceGetAttribute(&smcount, cudaDevAttrMultiProcessorCount, dev);

    size_t shmem = (size_t)SM_FLOATS * sizeof(float);   // 178688 B
    cudaFuncSetAttribute(se3_main, cudaFuncAttributeMaxDynamicSharedMemorySize, (int)shmem);
    se3_main<<<smcount, THREADS, shmem>>>(coords, rmask, nbrs, out);
}